// round 1
// baseline (speedup 1.0000x reference)
#include <cuda_runtime.h>

#define BB 32
#define IN_C 512
#define HW 4096
#define CODE 256
#define NCLASSES 4
#define MEMN 20
#define DECAYF 0.9f
#define EPSF 1e-12f
#define NTILES 32          // HW / 128 n-tiles in the GEMM

// Deterministic scratch (no atomics anywhere).
__device__ float g_partial[BB * CODE * NTILES];   // per-(b,o,ntile) masked partial sums
__device__ float g_queue[NCLASSES * MEMN * CODE]; // updated queue state

// labels may be int32 or int64 depending on jax x64 config; detect on device.
// int64 little-endian small values => every odd 32-bit word is zero.
__device__ __forceinline__ int get_label(const int* lab, int i) {
    bool odd_zero = true;
#pragma unroll
    for (int k = 1; k < 32; k += 2) odd_zero &= (lab[k] == 0);
    return odd_zero ? lab[2 * i] : lab[i];
}

// ---------------------------------------------------------------------------
// Kernel 1: batched 1x1-conv GEMM. Per batch: [256 x 512] @ [512 x 4096] + bias.
// Writes x into out channels [256, 512). Also emits per-block masked partials.
// Tiling: 128(o) x 128(n) x 16(k), 256 threads, 8x8 per-thread microtile.
// ---------------------------------------------------------------------------
__global__ __launch_bounds__(256) void gemm_proj_kernel(
    const float* __restrict__ feats, const float* __restrict__ preds,
    const float* __restrict__ Wp, const float* __restrict__ bp,
    float* __restrict__ out)
{
    const int nt = blockIdx.x;            // n tile (0..31)
    const int ot = blockIdx.y;            // o tile (0..1)
    const int b  = blockIdx.z;
    const int n0 = nt * 128;
    const int o0 = ot * 128;
    const int t  = threadIdx.x;
    const int tx = t & 15;                // n-direction (8 cols each)
    const int ty = t >> 4;                // o-direction (8 rows each)

    __shared__ float As[16][128];         // As[k][o] = Wp[o0+o][k0+k]
    __shared__ float Bs[16][128];         // Bs[k][n] = feats[b][k0+k][n0+n]

    float acc[8][8];
#pragma unroll
    for (int i = 0; i < 8; i++)
#pragma unroll
        for (int j = 0; j < 8; j++) acc[i][j] = 0.0f;

    const float* fb = feats + (long long)b * IN_C * HW;

    const int ar = t >> 1;                // 0..127  (Wp row within tile)
    const int ac = (t & 1) * 8;           // 0 or 8  (k offset)
    const int br = t >> 4;                // 0..15   (k row)
    const int bc = (t & 15) * 8;          // n offset

    for (int k0 = 0; k0 < IN_C; k0 += 16) {
        float4 av0 = *(const float4*)(Wp + (long long)(o0 + ar) * IN_C + k0 + ac);
        float4 av1 = *(const float4*)(Wp + (long long)(o0 + ar) * IN_C + k0 + ac + 4);
        float4 bv0 = *(const float4*)(fb + (long long)(k0 + br) * HW + n0 + bc);
        float4 bv1 = *(const float4*)(fb + (long long)(k0 + br) * HW + n0 + bc + 4);
        __syncthreads();
        As[ac + 0][ar] = av0.x; As[ac + 1][ar] = av0.y;
        As[ac + 2][ar] = av0.z; As[ac + 3][ar] = av0.w;
        As[ac + 4][ar] = av1.x; As[ac + 5][ar] = av1.y;
        As[ac + 6][ar] = av1.z; As[ac + 7][ar] = av1.w;
        *(float4*)&Bs[br][bc]     = bv0;
        *(float4*)&Bs[br][bc + 4] = bv1;
        __syncthreads();
#pragma unroll
        for (int kk = 0; kk < 16; kk++) {
            float a[8], bbv[8];
            *(float4*)(a)     = *(const float4*)&As[kk][ty * 8];
            *(float4*)(a + 4) = *(const float4*)&As[kk][ty * 8 + 4];
            *(float4*)(bbv)     = *(const float4*)&Bs[kk][tx * 8];
            *(float4*)(bbv + 4) = *(const float4*)&Bs[kk][tx * 8 + 4];
#pragma unroll
            for (int i = 0; i < 8; i++)
#pragma unroll
                for (int j = 0; j < 8; j++) acc[i][j] += a[i] * bbv[j];
        }
    }

    // Epilogue: bias, write x to out[b, 256+o, n], masked partial per o-row.
    float pv[8];
    *(float4*)(pv)     = *(const float4*)(preds + (long long)b * HW + n0 + tx * 8);
    *(float4*)(pv + 4) = *(const float4*)(preds + (long long)b * HW + n0 + tx * 8 + 4);

    float* ob = out + ((long long)b * 2 * CODE + CODE + o0) * HW;

#pragma unroll
    for (int i = 0; i < 8; i++) {
        const int orow = ty * 8 + i;
        const float bias = bp[o0 + orow];
        float rsum = 0.0f;
#pragma unroll
        for (int j = 0; j < 8; j++) {
            float v = acc[i][j] + bias;
            acc[i][j] = v;
            rsum += v * pv[j];
        }
        *(float4*)(ob + (long long)orow * HW + n0 + tx * 8)     = *(float4*)(&acc[i][0]);
        *(float4*)(ob + (long long)orow * HW + n0 + tx * 8 + 4) = *(float4*)(&acc[i][4]);
        // reduce rsum across the 16 tx lanes (same ty occupies a 16-lane half-warp)
#pragma unroll
        for (int off = 1; off < 16; off <<= 1)
            rsum += __shfl_xor_sync(0xffffffffu, rsum, off);
        if (tx == 0)
            g_partial[((long long)b * CODE + o0 + orow) * NTILES + nt] = rsum;
    }
}

// ---------------------------------------------------------------------------
// Kernel 2: sequential EMA queue update. One block, 672 threads (21 warps).
// ---------------------------------------------------------------------------
__global__ __launch_bounds__(672) void queue_update_kernel(
    const float* __restrict__ queue_in, const int* __restrict__ labels_raw,
    const int* __restrict__ flag)
{
    const int t = threadIdx.x;
    for (int i = t; i < NCLASSES * MEMN * CODE; i += 672) g_queue[i] = queue_in[i];

    __shared__ float sf[CODE];
    __shared__ float s_logit[MEMN];
    __shared__ float s_fnorm;
    __syncthreads();

    if (*flag != 1) return;

    const int warp = t >> 5, lane = t & 31;

    for (int b = 0; b < BB; b++) {
        const int l = get_label(labels_raw, b);
        // feat[b, c]: deterministic fixed-order reduce of 32 tile partials, /HW
        if (t < CODE) {
            const float* p = g_partial + ((long long)b * CODE + t) * NTILES;
            float s = 0.0f;
#pragma unroll
            for (int k = 0; k < NTILES; k++) s += p[k];
            sf[t] = s * (1.0f / HW);
        }
        __syncthreads();

        if (warp < MEMN) {                 // warps 0..19: logit[m] = slot[m] . f
            const float* slot = g_queue + ((long long)l * MEMN + warp) * CODE;
            float s = 0.0f;
            for (int c = lane; c < CODE; c += 32) s += slot[c] * sf[c];
#pragma unroll
            for (int off = 16; off; off >>= 1) s += __shfl_xor_sync(0xffffffffu, s, off);
            if (lane == 0) s_logit[warp] = s;
        } else {                           // warp 20: ||f||
            float s = 0.0f;
            for (int c = lane; c < CODE; c += 32) { float v = sf[c]; s += v * v; }
#pragma unroll
            for (int off = 16; off; off >>= 1) s += __shfl_xor_sync(0xffffffffu, s, off);
            if (lane == 0) s_fnorm = sqrtf(s);
        }
        __syncthreads();

        const float fn = s_fnorm;
        for (int i = t; i < MEMN * CODE; i += 672) {
            const int m = i >> 8, c = i & 255;
            const float lg = s_logit[m];
            const float denom = fmaxf(fabsf(lg) * fn, EPSF);
            const float upd = lg * sf[c] / denom;
            float* qp = g_queue + ((long long)l * MEMN + m) * CODE + c;
            *qp = DECAYF * (*qp) + (1.0f - DECAYF) * upd;
        }
        __syncthreads();
    }
}

// ---------------------------------------------------------------------------
// Kernel 3: memory attention. Grid (HW/1024, B), 256 threads.
// Each thread owns 4 consecutive n, holds all 20 logits in registers,
// softmax in registers, then new_feat = q^T @ attn into out channels [0,256).
// ---------------------------------------------------------------------------
__global__ __launch_bounds__(256) void attn_kernel(
    const int* __restrict__ labels_raw, float* __restrict__ out)
{
    const int b  = blockIdx.y;
    const int n0 = blockIdx.x * 1024;
    const int t  = threadIdx.x;

    __shared__ float sq[MEMN][CODE];
    const int l = get_label(labels_raw, b);
    const float* qsrc = g_queue + (long long)l * MEMN * CODE;
    for (int i = t * 4; i < MEMN * CODE; i += 1024)
        *(float4*)(&sq[0][0] + i) = *(const float4*)(qsrc + i);
    __syncthreads();

    const float* xb = out + ((long long)b * 2 * CODE + CODE) * HW;  // x half
    float*       ob = out + ((long long)b * 2 * CODE) * HW;         // new_feat half
    const int j = n0 + t * 4;

    float4 acc[MEMN];
#pragma unroll
    for (int m = 0; m < MEMN; m++) acc[m] = make_float4(0.f, 0.f, 0.f, 0.f);

#pragma unroll 4
    for (int c = 0; c < CODE; c++) {
        float4 xv = *(const float4*)(xb + (long long)c * HW + j);
#pragma unroll
        for (int m = 0; m < MEMN; m++) {
            float q = sq[m][c];
            acc[m].x += q * xv.x; acc[m].y += q * xv.y;
            acc[m].z += q * xv.z; acc[m].w += q * xv.w;
        }
    }

    // softmax over m (per lane of the float4), fully in registers
    float4 mx = acc[0];
#pragma unroll
    for (int m = 1; m < MEMN; m++) {
        mx.x = fmaxf(mx.x, acc[m].x); mx.y = fmaxf(mx.y, acc[m].y);
        mx.z = fmaxf(mx.z, acc[m].z); mx.w = fmaxf(mx.w, acc[m].w);
    }
    float4 s = make_float4(0.f, 0.f, 0.f, 0.f);
#pragma unroll
    for (int m = 0; m < MEMN; m++) {
        acc[m].x = expf(acc[m].x - mx.x); acc[m].y = expf(acc[m].y - mx.y);
        acc[m].z = expf(acc[m].z - mx.z); acc[m].w = expf(acc[m].w - mx.w);
        s.x += acc[m].x; s.y += acc[m].y; s.z += acc[m].z; s.w += acc[m].w;
    }
    const float4 inv = make_float4(1.f / s.x, 1.f / s.y, 1.f / s.z, 1.f / s.w);
#pragma unroll
    for (int m = 0; m < MEMN; m++) {
        acc[m].x *= inv.x; acc[m].y *= inv.y; acc[m].z *= inv.z; acc[m].w *= inv.w;
    }

    // new_feat[c, j..j+3] = sum_m q[m][c] * attn[m]
#pragma unroll 2
    for (int c = 0; c < CODE; c++) {
        float4 v = make_float4(0.f, 0.f, 0.f, 0.f);
#pragma unroll
        for (int m = 0; m < MEMN; m++) {
            float q = sq[m][c];
            v.x += q * acc[m].x; v.y += q * acc[m].y;
            v.z += q * acc[m].z; v.w += q * acc[m].w;
        }
        *(float4*)(ob + (long long)c * HW + j) = v;
    }
}

// ---------------------------------------------------------------------------
extern "C" void kernel_launch(void* const* d_in, const int* in_sizes, int n_in,
                              void* d_out, int out_size) {
    const float* feats  = (const float*)d_in[0];
    const float* preds  = (const float*)d_in[1];
    const int*   labels = (const int*)  d_in[2];  // width auto-detected on device
    const int*   flag   = (const int*)  d_in[3];
    const float* queue  = (const float*)d_in[4];
    const float* Wp     = (const float*)d_in[5];
    const float* bp     = (const float*)d_in[6];
    float* out = (float*)d_out;

    dim3 g1(HW / 128, CODE / 128, BB);
    gemm_proj_kernel<<<g1, 256>>>(feats, preds, Wp, bp, out);
    queue_update_kernel<<<1, 672>>>(queue, labels, flag);
    dim3 g3(HW / 1024, BB);
    attn_kernel<<<g3, 256>>>(labels, out);
}